// round 2
// baseline (speedup 1.0000x reference)
#include <cuda_runtime.h>

#define MAXN 100000
#define MAXE 1600000
#define D    128

// ---------------- scratch (device globals; fully rewritten each launch) ----
__device__ __align__(16) float g_deg[MAXN];
__device__ __align__(16) float g_dis[MAXN];
__device__ __align__(16) float g_xw  [(size_t)MAXN * D];   // current layer's x@W
__device__ __align__(16) float g_aggA[(size_t)MAXN * D];   // conv1 aggregation
__device__ __align__(16) float g_aggB[(size_t)MAXN * D];   // conv2 aggregation
__device__ int g_is64;                                     // edge dtype flag

// ---------------- edge dtype detection -------------------------------------
// If edge buffer is int64, high (odd little-endian) words of values < 100000
// are all zero. If int32, odd words are random node indices (virtually never
// all zero). Deterministic: same input -> same flag.
__global__ void k_detect(const int* __restrict__ e32, int nwords) {
    __shared__ int any;
    if (threadIdx.x == 0) any = 0;
    __syncthreads();
    int lim = nwords < 4096 ? nwords : 4096;
    for (int w = 1 + 2 * threadIdx.x; w < lim; w += 2 * blockDim.x) {
        if (e32[w] != 0) any = 1;
    }
    __syncthreads();
    if (threadIdx.x == 0) g_is64 = any ? 0 : 1;
}

__device__ __forceinline__ int edge_src(const int* e, int E, int i) {
    return g_is64 ? e[2 * (size_t)i] : e[i];
}
__device__ __forceinline__ int edge_dst(const int* e, int E, int i) {
    return g_is64 ? e[2 * ((size_t)E + i)] : e[(size_t)E + i];
}

// ---------------- degree / normalization ----------------------------------
__global__ void k_init_deg(int n) {
    int i = blockIdx.x * blockDim.x + threadIdx.x;
    if (i < n) g_deg[i] = 1.0f;  // self-loop
}

__global__ void k_count_deg(const int* __restrict__ edge, int E) {
    int i = blockIdx.x * blockDim.x + threadIdx.x;
    if (i < E) {
        int d = edge_dst(edge, E, i);
        atomicAdd(&g_deg[d], 1.0f);
    }
}

__global__ void k_dis(int n) {
    int i = blockIdx.x * blockDim.x + threadIdx.x;
    if (i < n) g_dis[i] = rsqrtf(g_deg[i]);
}

// ---------------- fused GEMM: C = f_in(A)@W, with epilogues ----------------
// f_in(a) = relu_in ? max(a + bias_in, 0) : a          (bias_in may be null)
// outP[row]   = relu_out ? max(C + bias_out, 0) : C+bias_out
// outAgg[row] = dis[row]^2 * C                          (if outAgg != null)
// Tile: 64 rows x 128 cols. 256 threads, 8x4 micro-tile per thread.
__global__ void k_gemm(const float* __restrict__ A,
                       const float* __restrict__ bias_in, int relu_in,
                       const float* __restrict__ W,
                       float* __restrict__ outP,
                       const float* __restrict__ bias_out, int relu_out,
                       float* __restrict__ outAgg,
                       int n)
{
    extern __shared__ float sh[];
    float* As = sh;                  // 64 * 129
    float* Ws = sh + 64 * 129;       // 128 * 128
    const int tid = threadIdx.x;
    const int rowBlock = blockIdx.x * 64;

    // load W (128x128 fp32 = 4096 float4)
    {
        const float4* W4 = (const float4*)W;
        float4* Ws4 = (float4*)Ws;
        #pragma unroll
        for (int i = 0; i < 16; i++) Ws4[tid + i * 256] = W4[tid + i * 256];
    }
    // load A tile (64 rows x 32 float4), fuse bias_in + relu_in
    #pragma unroll
    for (int i = 0; i < 8; i++) {
        int idx = tid + i * 256;     // 0..2047
        int r   = idx >> 5;          // 0..63
        int c4  = idx & 31;          // 0..31
        int grow = rowBlock + r;
        float4 v = make_float4(0.f, 0.f, 0.f, 0.f);
        if (grow < n) v = ((const float4*)(A + (size_t)grow * D))[c4];
        if (bias_in) {
            v.x += bias_in[c4 * 4 + 0]; v.y += bias_in[c4 * 4 + 1];
            v.z += bias_in[c4 * 4 + 2]; v.w += bias_in[c4 * 4 + 3];
        }
        if (relu_in) {
            v.x = fmaxf(v.x, 0.f); v.y = fmaxf(v.y, 0.f);
            v.z = fmaxf(v.z, 0.f); v.w = fmaxf(v.w, 0.f);
        }
        float* ap = As + r * 129 + c4 * 4;
        ap[0] = v.x; ap[1] = v.y; ap[2] = v.z; ap[3] = v.w;
    }
    __syncthreads();

    const int rg = tid >> 5;   // 0..7  (rows rg + r*8)
    const int cg = tid & 31;   // cols cg*4 .. cg*4+3

    float acc[8][4];
    #pragma unroll
    for (int r = 0; r < 8; r++)
        #pragma unroll
        for (int c = 0; c < 4; c++) acc[r][c] = 0.f;

    const float4* WsV = (const float4*)Ws;
    #pragma unroll 8
    for (int k = 0; k < 128; k++) {
        float4 b = WsV[k * 32 + cg];
        float a[8];
        #pragma unroll
        for (int r = 0; r < 8; r++) a[r] = As[(rg + r * 8) * 129 + k];
        #pragma unroll
        for (int r = 0; r < 8; r++) {
            acc[r][0] = fmaf(a[r], b.x, acc[r][0]);
            acc[r][1] = fmaf(a[r], b.y, acc[r][1]);
            acc[r][2] = fmaf(a[r], b.z, acc[r][2]);
            acc[r][3] = fmaf(a[r], b.w, acc[r][3]);
        }
    }

    // epilogue
    const int col = cg * 4;
    float4 bo = make_float4(0.f, 0.f, 0.f, 0.f);
    if (bias_out) {
        bo.x = bias_out[col + 0]; bo.y = bias_out[col + 1];
        bo.z = bias_out[col + 2]; bo.w = bias_out[col + 3];
    }
    #pragma unroll
    for (int r = 0; r < 8; r++) {
        int grow = rowBlock + rg + r * 8;
        if (grow >= n) continue;
        float4 c;
        c.x = acc[r][0]; c.y = acc[r][1]; c.z = acc[r][2]; c.w = acc[r][3];
        if (outAgg) {
            float d2 = g_dis[grow]; d2 *= d2;
            float4 ag;
            ag.x = c.x * d2; ag.y = c.y * d2; ag.z = c.z * d2; ag.w = c.w * d2;
            ((float4*)(outAgg + (size_t)grow * D))[cg] = ag;
        }
        float4 o;
        o.x = c.x + bo.x; o.y = c.y + bo.y; o.z = c.z + bo.z; o.w = c.w + bo.w;
        if (relu_out) {
            o.x = fmaxf(o.x, 0.f); o.y = fmaxf(o.y, 0.f);
            o.z = fmaxf(o.z, 0.f); o.w = fmaxf(o.w, 0.f);
        }
        ((float4*)(outP + (size_t)grow * D))[cg] = o;
    }
}

// ---------------- edge scatter: agg[dst] += dis[src]*dis[dst] * xw[src] ----
__global__ void k_scatter(const float* __restrict__ xw,
                          float* __restrict__ agg,
                          const int* __restrict__ edge, int E)
{
    int warp = (blockIdx.x * blockDim.x + threadIdx.x) >> 5;
    int lane = threadIdx.x & 31;
    if (warp >= E) return;
    int s = 0, d = 0;
    float coef = 0.f;
    if (lane == 0) {
        s = edge_src(edge, E, warp);
        d = edge_dst(edge, E, warp);
        coef = g_dis[s] * g_dis[d];
    }
    s    = __shfl_sync(0xFFFFFFFFu, s, 0);
    d    = __shfl_sync(0xFFFFFFFFu, d, 0);
    coef = __shfl_sync(0xFFFFFFFFu, coef, 0);

    float4 v = ((const float4*)(xw + (size_t)s * D))[lane];
    v.x *= coef; v.y *= coef; v.z *= coef; v.w *= coef;
    float* out = agg + (size_t)d * D + lane * 4;
    asm volatile("red.global.add.v4.f32 [%0], {%1,%2,%3,%4};"
                 :: "l"(out), "f"(v.x), "f"(v.y), "f"(v.z), "f"(v.w)
                 : "memory");
}

// ---------------- h = aggB + b2 -> out[0] ----------------------------------
__global__ void k_h_out(const float* __restrict__ agg,
                        const float* __restrict__ b2,
                        float* __restrict__ out, int total)
{
    int i = blockIdx.x * blockDim.x + threadIdx.x;
    if (i < total) out[i] = agg[i] + b2[i & (D - 1)];
}

// ---------------- launch ---------------------------------------------------
extern "C" void kernel_launch(void* const* d_in, const int* in_sizes, int n_in,
                              void* d_out, int out_size)
{
    const float* x    = (const float*)d_in[0];
    const int*   edge = (const int*)d_in[1];   // int32 or int64 (detected)
    const float* W1 = (const float*)d_in[2]; const float* b1 = (const float*)d_in[3];
    const float* W2 = (const float*)d_in[4]; const float* b2 = (const float*)d_in[5];
    const float* Wv = (const float*)d_in[6]; const float* bv = (const float*)d_in[7];
    const float* Wt = (const float*)d_in[8]; const float* bt = (const float*)d_in[9];

    const int n = in_sizes[0] / D;
    const int E = in_sizes[1] / 2;   // element count is 2E for either dtype

    float* out_h = (float*)d_out;
    float* out_v = out_h + (size_t)n * D;
    float* out_t = out_v + (size_t)n * D;

    float* xw   = nullptr; cudaGetSymbolAddress((void**)&xw,   g_xw);
    float* aggA = nullptr; cudaGetSymbolAddress((void**)&aggA, g_aggA);
    float* aggB = nullptr; cudaGetSymbolAddress((void**)&aggB, g_aggB);

    const size_t SMEM = (64 * 129 + 128 * 128) * sizeof(float);
    cudaFuncSetAttribute(k_gemm, cudaFuncAttributeMaxDynamicSharedMemorySize, (int)SMEM);

    const int TB = 256;
    // 0) edge dtype detection
    k_detect<<<1, 512>>>(edge, 2 * E);
    // 1) degrees + rsqrt
    k_init_deg<<<(n + TB - 1) / TB, TB>>>(n);
    k_count_deg<<<(E + TB - 1) / TB, TB>>>(edge, E);
    k_dis<<<(n + TB - 1) / TB, TB>>>(n);

    const int gemmGrid = (n + 63) / 64;
    // 2) conv1: xw1 = x@W1 ; aggA = dis^2*xw1 (epilogue) ; scatter
    k_gemm<<<gemmGrid, TB, SMEM>>>(x, nullptr, 0, W1, xw, nullptr, 0, aggA, n);
    {
        long long threads = (long long)E * 32;
        int blocks = (int)((threads + TB - 1) / TB);
        k_scatter<<<blocks, TB>>>(xw, aggA, edge, E);
    }
    // 3) conv2: A = relu(aggA+b1) ; xw2 = A@W2 ; aggB = dis^2*xw2 ; scatter
    k_gemm<<<gemmGrid, TB, SMEM>>>(aggA, b1, 1, W2, xw, nullptr, 0, aggB, n);
    {
        long long threads = (long long)E * 32;
        int blocks = (int)((threads + TB - 1) / TB);
        k_scatter<<<blocks, TB>>>(xw, aggB, edge, E);
    }
    // 4) h = aggB + b2 -> out[0]
    k_h_out<<<((n * D) + TB - 1) / TB, TB>>>(aggB, b2, out_h, n * D);
    // 5) heads: relu(h@Wv+bv), relu(h@Wt+bt)
    k_gemm<<<gemmGrid, TB, SMEM>>>(out_h, nullptr, 0, Wv, out_v, bv, 1, nullptr, n);
    k_gemm<<<gemmGrid, TB, SMEM>>>(out_h, nullptr, 0, Wt, out_t, bt, 1, nullptr, n);
}

// round 3
// speedup vs baseline: 1.7149x; 1.7149x over previous
#include <cuda_runtime.h>

#define MAXN 100000
#define MAXE 1600000
#define D    128
#define SCAN_BS 512
#define MAX_SCAN_BLOCKS 256

// ---------------- scratch (device globals; fully rewritten each launch) ----
__device__ __align__(16) float g_dis[MAXN];
__device__ __align__(16) float g_xw [(size_t)MAXN * D];   // current layer's x@W
__device__ __align__(16) float g_h  [(size_t)MAXN * D];   // conv1 output (relu'd)
__device__ int   g_cnt[MAXN];
__device__ int   g_incl[MAXN];
__device__ int   g_bsum[MAX_SCAN_BLOCKS];
__device__ int   g_rowstart[MAXN + 1];
__device__ int   g_cursor[MAXN];
__device__ __align__(8) int   g_csr_src[MAXE];
__device__ __align__(8) float g_csr_coef[MAXE];
__device__ int g_is64;                                    // edge dtype flag

// ---------------- edge dtype detection -------------------------------------
__global__ void k_detect(const int* __restrict__ e32, int nwords) {
    __shared__ int any;
    if (threadIdx.x == 0) any = 0;
    __syncthreads();
    int lim = nwords < 4096 ? nwords : 4096;
    for (int w = 1 + 2 * threadIdx.x; w < lim; w += 2 * blockDim.x)
        if (e32[w] != 0) any = 1;
    __syncthreads();
    if (threadIdx.x == 0) g_is64 = any ? 0 : 1;
}

__device__ __forceinline__ int edge_src(const int* e, int E, int i) {
    return g_is64 ? e[2 * (size_t)i] : e[i];
}
__device__ __forceinline__ int edge_dst(const int* e, int E, int i) {
    return g_is64 ? e[2 * ((size_t)E + i)] : e[(size_t)E + i];
}

// ---------------- CSR build -------------------------------------------------
__global__ void k_zero(int n) {
    int i = blockIdx.x * blockDim.x + threadIdx.x;
    if (i < n) { g_cnt[i] = 0; g_cursor[i] = 0; }
}

__global__ void k_hist(const int* __restrict__ edge, int E) {
    int i = blockIdx.x * blockDim.x + threadIdx.x;
    if (i < E) atomicAdd(&g_cnt[edge_dst(edge, E, i)], 1);
}

__global__ void k_dis(int n) {
    int i = blockIdx.x * blockDim.x + threadIdx.x;
    if (i < n) g_dis[i] = rsqrtf((float)g_cnt[i] + 1.0f);
}

// inclusive scan within blocks of SCAN_BS
__global__ void k_scan_block(int n) {
    __shared__ int sh[SCAN_BS];
    int i = blockIdx.x * SCAN_BS + threadIdx.x;
    int v = (i < n) ? g_cnt[i] : 0;
    sh[threadIdx.x] = v;
    __syncthreads();
    #pragma unroll
    for (int off = 1; off < SCAN_BS; off <<= 1) {
        int t = (threadIdx.x >= off) ? sh[threadIdx.x - off] : 0;
        __syncthreads();
        sh[threadIdx.x] += t;
        __syncthreads();
    }
    if (i < n) g_incl[i] = sh[threadIdx.x];
    if (threadIdx.x == SCAN_BS - 1) g_bsum[blockIdx.x] = sh[threadIdx.x];
}

// exclusive scan of block sums (single block)
__global__ void k_scan_tops(int nblocks) {
    __shared__ int sh[MAX_SCAN_BLOCKS];
    int v = (threadIdx.x < nblocks) ? g_bsum[threadIdx.x] : 0;
    sh[threadIdx.x] = v;
    __syncthreads();
    #pragma unroll
    for (int off = 1; off < MAX_SCAN_BLOCKS; off <<= 1) {
        int t = (threadIdx.x >= off) ? sh[threadIdx.x - off] : 0;
        __syncthreads();
        sh[threadIdx.x] += t;
        __syncthreads();
    }
    g_bsum[threadIdx.x] = sh[threadIdx.x] - v;  // exclusive
}

__global__ void k_scan_add(int n, int E) {
    int i = blockIdx.x * SCAN_BS + threadIdx.x;
    if (i < n) {
        int excl = g_incl[i] - g_cnt[i] + g_bsum[blockIdx.x];
        g_rowstart[i] = excl;
        if (i == n - 1) g_rowstart[n] = excl + g_cnt[i];
    }
}

__global__ void k_fill(const int* __restrict__ edge, int E) {
    int i = blockIdx.x * blockDim.x + threadIdx.x;
    if (i < E) {
        int s = edge_src(edge, E, i);
        int d = edge_dst(edge, E, i);
        int pos = g_rowstart[d] + atomicAdd(&g_cursor[d], 1);
        g_csr_src[pos]  = s;
        g_csr_coef[pos] = g_dis[s] * g_dis[d];
    }
}

// ---------------- GEMM: C = A@W (no epilogue) ------------------------------
// Tile: 64 rows x 128 cols. 256 threads, 8x4 micro-tile per thread.
__global__ void k_gemm(const float* __restrict__ A,
                       const float* __restrict__ W,
                       float* __restrict__ C, int n)
{
    extern __shared__ float sh[];
    float* As = sh;                  // 64 * 129
    float* Ws = sh + 64 * 129;       // 128 * 128
    const int tid = threadIdx.x;
    const int rowBlock = blockIdx.x * 64;

    {
        const float4* W4 = (const float4*)W;
        float4* Ws4 = (float4*)Ws;
        #pragma unroll
        for (int i = 0; i < 16; i++) Ws4[tid + i * 256] = W4[tid + i * 256];
    }
    #pragma unroll
    for (int i = 0; i < 8; i++) {
        int idx = tid + i * 256;
        int r   = idx >> 5;
        int c4  = idx & 31;
        int grow = rowBlock + r;
        float4 v = make_float4(0.f, 0.f, 0.f, 0.f);
        if (grow < n) v = ((const float4*)(A + (size_t)grow * D))[c4];
        float* ap = As + r * 129 + c4 * 4;
        ap[0] = v.x; ap[1] = v.y; ap[2] = v.z; ap[3] = v.w;
    }
    __syncthreads();

    const int rg = tid >> 5;
    const int cg = tid & 31;
    float acc[8][4];
    #pragma unroll
    for (int r = 0; r < 8; r++)
        #pragma unroll
        for (int c = 0; c < 4; c++) acc[r][c] = 0.f;

    const float4* WsV = (const float4*)Ws;
    #pragma unroll 8
    for (int k = 0; k < 128; k++) {
        float4 b = WsV[k * 32 + cg];
        float a[8];
        #pragma unroll
        for (int r = 0; r < 8; r++) a[r] = As[(rg + r * 8) * 129 + k];
        #pragma unroll
        for (int r = 0; r < 8; r++) {
            acc[r][0] = fmaf(a[r], b.x, acc[r][0]);
            acc[r][1] = fmaf(a[r], b.y, acc[r][1]);
            acc[r][2] = fmaf(a[r], b.z, acc[r][2]);
            acc[r][3] = fmaf(a[r], b.w, acc[r][3]);
        }
    }

    #pragma unroll
    for (int r = 0; r < 8; r++) {
        int grow = rowBlock + rg + r * 8;
        if (grow >= n) continue;
        float4 o;
        o.x = acc[r][0]; o.y = acc[r][1]; o.z = acc[r][2]; o.w = acc[r][3];
        ((float4*)(C + (size_t)grow * D))[cg] = o;
    }
}

// ---------------- fused dual GEMM for the two heads ------------------------
// outV = relu(A@Wv + bv), outT = relu(A@Wt + bt)
__global__ void k_gemm2(const float* __restrict__ A,
                        const float* __restrict__ Wv, const float* __restrict__ bv,
                        float* __restrict__ outV,
                        const float* __restrict__ Wt, const float* __restrict__ bt,
                        float* __restrict__ outT, int n)
{
    extern __shared__ float sh[];
    float* As  = sh;                      // 64 * 129
    float* WsV = sh + 64 * 129;           // 128 * 128
    float* WsT = WsV + 128 * 128;         // 128 * 128
    const int tid = threadIdx.x;
    const int rowBlock = blockIdx.x * 64;

    {
        const float4* Wv4 = (const float4*)Wv;
        const float4* Wt4 = (const float4*)Wt;
        float4* v4 = (float4*)WsV;
        float4* t4 = (float4*)WsT;
        #pragma unroll
        for (int i = 0; i < 16; i++) {
            v4[tid + i * 256] = Wv4[tid + i * 256];
            t4[tid + i * 256] = Wt4[tid + i * 256];
        }
    }
    #pragma unroll
    for (int i = 0; i < 8; i++) {
        int idx = tid + i * 256;
        int r   = idx >> 5;
        int c4  = idx & 31;
        int grow = rowBlock + r;
        float4 v = make_float4(0.f, 0.f, 0.f, 0.f);
        if (grow < n) v = ((const float4*)(A + (size_t)grow * D))[c4];
        float* ap = As + r * 129 + c4 * 4;
        ap[0] = v.x; ap[1] = v.y; ap[2] = v.z; ap[3] = v.w;
    }
    __syncthreads();

    const int rg = tid >> 5;
    const int cg = tid & 31;
    float accV[8][4], accT[8][4];
    #pragma unroll
    for (int r = 0; r < 8; r++)
        #pragma unroll
        for (int c = 0; c < 4; c++) { accV[r][c] = 0.f; accT[r][c] = 0.f; }

    const float4* Vv = (const float4*)WsV;
    const float4* Vt = (const float4*)WsT;
    #pragma unroll 4
    for (int k = 0; k < 128; k++) {
        float4 wv = Vv[k * 32 + cg];
        float4 wt = Vt[k * 32 + cg];
        float a[8];
        #pragma unroll
        for (int r = 0; r < 8; r++) a[r] = As[(rg + r * 8) * 129 + k];
        #pragma unroll
        for (int r = 0; r < 8; r++) {
            accV[r][0] = fmaf(a[r], wv.x, accV[r][0]);
            accV[r][1] = fmaf(a[r], wv.y, accV[r][1]);
            accV[r][2] = fmaf(a[r], wv.z, accV[r][2]);
            accV[r][3] = fmaf(a[r], wv.w, accV[r][3]);
            accT[r][0] = fmaf(a[r], wt.x, accT[r][0]);
            accT[r][1] = fmaf(a[r], wt.y, accT[r][1]);
            accT[r][2] = fmaf(a[r], wt.z, accT[r][2]);
            accT[r][3] = fmaf(a[r], wt.w, accT[r][3]);
        }
    }

    const int col = cg * 4;
    float4 bvv = make_float4(bv[col], bv[col+1], bv[col+2], bv[col+3]);
    float4 btt = make_float4(bt[col], bt[col+1], bt[col+2], bt[col+3]);
    #pragma unroll
    for (int r = 0; r < 8; r++) {
        int grow = rowBlock + rg + r * 8;
        if (grow >= n) continue;
        float4 ov, ot;
        ov.x = fmaxf(accV[r][0] + bvv.x, 0.f);
        ov.y = fmaxf(accV[r][1] + bvv.y, 0.f);
        ov.z = fmaxf(accV[r][2] + bvv.z, 0.f);
        ov.w = fmaxf(accV[r][3] + bvv.w, 0.f);
        ot.x = fmaxf(accT[r][0] + btt.x, 0.f);
        ot.y = fmaxf(accT[r][1] + btt.y, 0.f);
        ot.z = fmaxf(accT[r][2] + btt.z, 0.f);
        ot.w = fmaxf(accT[r][3] + btt.w, 0.f);
        ((float4*)(outV + (size_t)grow * D))[cg] = ov;
        ((float4*)(outT + (size_t)grow * D))[cg] = ot;
    }
}

// ---------------- CSR gather aggregation -----------------------------------
// out[d] = f( dis[d]^2 * xw[d] + sum_e coef[e]*xw[src[e]] + bias ), f=relu?
// One warp per dst node; lane owns 4 consecutive floats (float4).
__global__ void k_gather(const float* __restrict__ xw,
                         float* __restrict__ out,
                         const float* __restrict__ bias, int relu,
                         int n)
{
    int warp = (blockIdx.x * blockDim.x + threadIdx.x) >> 5;
    int lane = threadIdx.x & 31;
    if (warp >= n) return;
    const int d = warp;

    float dis = g_dis[d];
    float dis2 = dis * dis;
    float4 self = ((const float4*)(xw + (size_t)d * D))[lane];
    float4 acc;
    acc.x = self.x * dis2; acc.y = self.y * dis2;
    acc.z = self.z * dis2; acc.w = self.w * dis2;

    int e   = g_rowstart[d];
    int end = g_rowstart[d + 1];

    // unrolled-by-2 for load pipelining
    for (; e + 1 < end; e += 2) {
        int   s0 = g_csr_src[e],     s1 = g_csr_src[e + 1];
        float c0 = g_csr_coef[e],    c1 = g_csr_coef[e + 1];
        float4 v0 = ((const float4*)(xw + (size_t)s0 * D))[lane];
        float4 v1 = ((const float4*)(xw + (size_t)s1 * D))[lane];
        acc.x = fmaf(c0, v0.x, acc.x); acc.y = fmaf(c0, v0.y, acc.y);
        acc.z = fmaf(c0, v0.z, acc.z); acc.w = fmaf(c0, v0.w, acc.w);
        acc.x = fmaf(c1, v1.x, acc.x); acc.y = fmaf(c1, v1.y, acc.y);
        acc.z = fmaf(c1, v1.z, acc.z); acc.w = fmaf(c1, v1.w, acc.w);
    }
    if (e < end) {
        int   s0 = g_csr_src[e];
        float c0 = g_csr_coef[e];
        float4 v0 = ((const float4*)(xw + (size_t)s0 * D))[lane];
        acc.x = fmaf(c0, v0.x, acc.x); acc.y = fmaf(c0, v0.y, acc.y);
        acc.z = fmaf(c0, v0.z, acc.z); acc.w = fmaf(c0, v0.w, acc.w);
    }

    const int col = lane * 4;
    acc.x += bias[col]; acc.y += bias[col + 1];
    acc.z += bias[col + 2]; acc.w += bias[col + 3];
    if (relu) {
        acc.x = fmaxf(acc.x, 0.f); acc.y = fmaxf(acc.y, 0.f);
        acc.z = fmaxf(acc.z, 0.f); acc.w = fmaxf(acc.w, 0.f);
    }
    ((float4*)(out + (size_t)d * D))[lane] = acc;
}

// ---------------- launch ---------------------------------------------------
extern "C" void kernel_launch(void* const* d_in, const int* in_sizes, int n_in,
                              void* d_out, int out_size)
{
    const float* x    = (const float*)d_in[0];
    const int*   edge = (const int*)d_in[1];   // int32 or int64 (detected)
    const float* W1 = (const float*)d_in[2]; const float* b1 = (const float*)d_in[3];
    const float* W2 = (const float*)d_in[4]; const float* b2 = (const float*)d_in[5];
    const float* Wv = (const float*)d_in[6]; const float* bv = (const float*)d_in[7];
    const float* Wt = (const float*)d_in[8]; const float* bt = (const float*)d_in[9];

    const int n = in_sizes[0] / D;
    const int E = in_sizes[1] / 2;

    float* out_h = (float*)d_out;
    float* out_v = out_h + (size_t)n * D;
    float* out_t = out_v + (size_t)n * D;

    float* xw = nullptr; cudaGetSymbolAddress((void**)&xw, g_xw);
    float* h  = nullptr; cudaGetSymbolAddress((void**)&h,  g_h);

    const size_t SMEM1 = (64 * 129 + 128 * 128) * sizeof(float);
    const size_t SMEM2 = (64 * 129 + 2 * 128 * 128) * sizeof(float);
    cudaFuncSetAttribute(k_gemm,  cudaFuncAttributeMaxDynamicSharedMemorySize, (int)SMEM1);
    cudaFuncSetAttribute(k_gemm2, cudaFuncAttributeMaxDynamicSharedMemorySize, (int)SMEM2);

    const int TB = 256;
    const int nscan = (n + SCAN_BS - 1) / SCAN_BS;

    // 0) dtype + CSR build + normalization
    k_detect<<<1, 512>>>(edge, 2 * E);
    k_zero<<<(n + TB - 1) / TB, TB>>>(n);
    k_hist<<<(E + TB - 1) / TB, TB>>>(edge, E);
    k_dis<<<(n + TB - 1) / TB, TB>>>(n);
    k_scan_block<<<nscan, SCAN_BS>>>(n);
    k_scan_tops<<<1, MAX_SCAN_BLOCKS>>>(nscan);
    k_scan_add<<<nscan, SCAN_BS>>>(n, E);
    k_fill<<<(E + TB - 1) / TB, TB>>>(edge, E);

    const int gemmGrid   = (n + 63) / 64;
    const int gatherGrid = (n + 7) / 8;   // 8 warps / block

    // conv1: xw = x@W1 ; h = relu(agg + b1)
    k_gemm<<<gemmGrid, TB, SMEM1>>>(x, W1, xw, n);
    k_gather<<<gatherGrid, TB>>>(xw, h, b1, 1, n);
    // conv2: xw = h@W2 ; out_h = agg + b2
    k_gemm<<<gemmGrid, TB, SMEM1>>>(h, W2, xw, n);
    k_gather<<<gatherGrid, TB>>>(xw, out_h, b2, 0, n);
    // heads (fused): out_v = relu(out_h@Wv+bv), out_t = relu(out_h@Wt+bt)
    k_gemm2<<<gemmGrid, TB, SMEM2>>>(out_h, Wv, bv, out_v, Wt, bt, out_t, n);
}